// round 12
// baseline (speedup 1.0000x reference)
#include <cuda_runtime.h>
#include <math_constants.h>

#define HH 1024
#define WW 1024
#define CC 128
#define NITER 8
#define TWO_RHO 71.6f         // 2 * sqrt(16^2 + 32^2) for a 32x64 region
#define FULLM 0xFFFFFFFFu
#define NBLK 512              // one CTA per 32-row x 64-col region

// 4 rotating cluster position buffers (row,col interleaved).
// Invariant: g_pos[1] is all-zero at kernel entry (static init covers the
// first run; block 0 re-zeroes it at k==6 each run for the next replay).
__device__ float g_pos[4][2 * CC];
// software grid barrier: counter and generation on SEPARATE 128B lines
__device__ __align__(128) unsigned g_cnt[32];
__device__ __align__(128) unsigned g_gen[32];

__device__ __forceinline__ unsigned ld_acquire_gpu(const unsigned* p) {
    unsigned v;
    asm volatile("ld.acquire.gpu.u32 %0, [%1];" : "=r"(v) : "l"(p) : "memory");
    return v;
}

// All cross-CTA data traffic is L2-native (global atomics + __ldcg), so
// scoped release/acquire atomics give full ordering with no membar/CCTL.
__device__ __forceinline__ void grid_barrier(unsigned target) {
    __syncthreads();
    if (threadIdx.x == 0) {
        unsigned old;
        asm volatile("atom.add.acq_rel.gpu.u32 %0, [%1], %2;"
                     : "=r"(old) : "l"(&g_cnt[0]), "r"(1u) : "memory");
        if (old == NBLK - 1u) {
            asm volatile("st.relaxed.gpu.u32 [%0], %1;"
                         :: "l"(&g_cnt[0]), "r"(0u) : "memory");
            asm volatile("red.add.release.gpu.u32 [%0], %1;"
                         :: "l"(&g_gen[0]), "r"(1u) : "memory");
        } else {
            unsigned g = ld_acquire_gpu(&g_gen[0]);
            int spins = 0;
            while ((int)(g - target) < 0) {
                if (++spins > 4) __nanosleep(40);   // hot-spin first, then doze
                g = ld_acquire_gpu(&g_gen[0]);
            }
        }
    }
    __syncthreads();
}

// warp-wide min of a uint (nonneg float bits are order-isomorphic)
__device__ __forceinline__ unsigned warp_min_u32(unsigned v) {
    unsigned r;
    asm volatile("redux.sync.min.u32 %0, %1, 0xffffffff;" : "=r"(r) : "r"(v));
    return r;
}

__global__ void __launch_bounds__(256, 4) km_all_kernel(
    const float* __restrict__ clusters,
    const float* __restrict__ heatmap,
    float* __restrict__ out)
{
    __shared__ float2   s_cand[CC];     // 4 per-warp segments of 32
    __shared__ int      s_cidx[CC];
    __shared__ float    s_acc[2 * CC];
    __shared__ int      s_cnt[4];
    __shared__ unsigned s_wmin[4];
    __shared__ unsigned s_zmask[4];

    const int t = threadIdx.x;
    const int wid = t >> 5;
    const int lane = t & 31;
    // 32-row x 64-col region per CTA; 8 consecutive pixels per thread
    const int region_c = (blockIdx.x & 15) * 64;
    const int region_r = (blockIdx.x >> 4) * 32;
    const int row  = region_r + (t >> 3);
    const int col0 = region_c + (t & 7) * 8;
    const float frow = (float)row;
    const float fc0  = (float)col0;
    const float cy = (float)region_r + 15.5f;
    const float cx = (float)region_c + 31.5f;

    // heatmap values for this thread's 8 pixels: constant across iterations
    float h[8];
    {
        const float4 a = *reinterpret_cast<const float4*>(heatmap + row * WW + col0);
        const float4 b = *reinterpret_cast<const float4*>(heatmap + row * WW + col0 + 4);
        h[0] = a.x; h[1] = a.y; h[2] = a.z; h[3] = a.w;
        h[4] = b.x; h[5] = b.y; h[6] = b.z; h[7] = b.w;
    }

    // base generation (monotone across replays); every CTA reads it before any
    // bump can occur (a bump needs all NBLK arrivals, each preceded by a read)
    unsigned tgt = ld_acquire_gpu(&g_gen[0]);

    #pragma unroll 1
    for (int k = 0; k < NITER; ++k) {
        const float* cin = (k == 0) ? clusters : &g_pos[k & 3][0];
        float* cout = (k == NITER - 1) ? out : &g_pos[(k + 1) & 3][0];

        s_acc[t] = 0.0f;

        // ---- Phase A: cull + O(1) zero-dup, per-warp segment compaction ----
        float d2c = CUDART_INF_F;
        float2 cpos = make_float2(0.f, 0.f);
        bool iszero = false;
        if (t < CC) {
            // L2 load: positions were produced by global atomics on other SMs
            cpos = __ldcg(reinterpret_cast<const float2*>(cin) + t);
            iszero = (cpos.x == 0.0f) && (cpos.y == 0.0f);
            const float dr = cy - cpos.x, dc = cx - cpos.y;
            d2c = fmaf(dr, dr, dc * dc);
        }
        const unsigned zb = __ballot_sync(FULLM, iszero);
        const unsigned mb = warp_min_u32(__float_as_uint(d2c));
        if ((lane == 0) && (wid < 4)) { s_wmin[wid] = mb; s_zmask[wid] = zb; }
        __syncthreads();                                    // sync #1

        if (t < CC) {                                       // warps 0-3 (uniform)
            unsigned mdu = s_wmin[0];
            #pragma unroll
            for (int w = 1; w < 4; ++w) mdu = min(mdu, s_wmin[w]);
            const float md2 = __uint_as_float(mdu);

            // first exactly-(0,0) cluster (empty clusters collapse there);
            // later (0,0) dups can never win strict-< argmin -> drop them.
            // Other bitwise dups are rare and harmless (strict < keeps first).
            int firstZero = 1 << 30;
            #pragma unroll
            for (int w = 3; w >= 0; --w)
                if (s_zmask[w]) firstZero = w * 32 + (__ffs(s_zmask[w]) - 1);

            // cluster can win argmin for some pixel in region only if
            // d(center,c) <= minD + 2*rho; margin keeps fp error conservative
            const float minD = sqrtf(md2);
            const float thr  = minD + TWO_RHO + 4.0f + 1e-5f * minD;
            const float thr2 = thr * thr;

            const bool keep = (d2c <= thr2) && !(iszero && t != firstZero);
            const unsigned bq = __ballot_sync(FULLM, keep);
            if (keep) {
                // per-warp segment: no cross-warp rank needed
                const int r = wid * 32 + __popc(bq & ((1u << lane) - 1u));
                s_cand[r] = cpos;
                s_cidx[r] = t;
            }
            if (lane == 0) s_cnt[wid] = __popc(bq);
        }
        __syncthreads();                                    // sync #2

        // ---- Phase B: 8-pixel argmin over 4 ordered segments ----
        // ascending (segment, rank) preserves ascending original index order
        float b[8];
        int   kk[8];
        #pragma unroll
        for (int q = 0; q < 8; ++q) { b[q] = CUDART_INF_F; kk[q] = 0; }

        #pragma unroll 1
        for (int w = 0; w < 4; ++w) {
            const int base = w * 32;
            const int nseg = s_cnt[w];
            #pragma unroll 2
            for (int j = 0; j < nseg; ++j) {
                const float2 cl = s_cand[base + j];
                const float dr = frow - cl.x;
                const float dr2 = dr * dr;
                #pragma unroll
                for (int q = 0; q < 8; ++q) {
                    // ordering of max(1,sqrt(d2)) == ordering of max(1,d2)
                    const float dc = (fc0 + (float)q) - cl.y;
                    const float d = fmaxf(fmaf(dc, dc, dr2), 1.0f);
                    if (d < b[q]) { b[q] = d; kk[q] = base + j; }
                }
            }
        }

        int idx[8];
        float w8[8];
        #pragma unroll
        for (int q = 0; q < 8; ++q) {
            idx[q] = s_cidx[kk[q]];
            // weight = heatmap / max(1,sqrt(d2)) = h * rsqrt(clamped d2)
            w8[q] = h[q] * rsqrtf(b[q]);
        }

        // ---- scatter: uniform-warp fast path, run-length fallback ----
        bool uni = true;
        #pragma unroll
        for (int q = 1; q < 8; ++q) uni = uni && (idx[q] == idx[0]);
        const int  u      = __shfl_sync(FULLM, idx[0], 0);
        const bool alluni = __all_sync(FULLM, uni && (idx[0] == u));

        if (alluni) {
            float wsum = ((w8[0] + w8[1]) + (w8[2] + w8[3]))
                       + ((w8[4] + w8[5]) + (w8[6] + w8[7]));
            float csum = 0.0f;
            #pragma unroll
            for (int q = 0; q < 8; ++q) csum = fmaf(fc0 + (float)q, w8[q], csum);
            float rsum = frow * wsum;
            #pragma unroll
            for (int o = 16; o; o >>= 1) {
                rsum += __shfl_xor_sync(FULLM, rsum, o);
                csum += __shfl_xor_sync(FULLM, csum, o);
            }
            if (lane == 0) {
                atomicAdd(&s_acc[2 * u],     rsum);
                atomicAdd(&s_acc[2 * u + 1], csum);
            }
        } else {
            int cur = idx[0];
            float wsum = w8[0], cwsum = fc0 * w8[0];
            #pragma unroll
            for (int q = 1; q < 8; ++q) {
                const float fcq = fc0 + (float)q;
                if (idx[q] == cur) { wsum += w8[q]; cwsum = fmaf(fcq, w8[q], cwsum); }
                else {
                    atomicAdd(&s_acc[2 * cur],     frow * wsum);
                    atomicAdd(&s_acc[2 * cur + 1], cwsum);
                    cur = idx[q]; wsum = w8[q]; cwsum = fcq * w8[q];
                }
            }
            atomicAdd(&s_acc[2 * cur],     frow * wsum);
            atomicAdd(&s_acc[2 * cur + 1], cwsum);
        }

        __syncthreads();
        // global accumulate; skip zeros (all contributions are >= +0)
        const float v = s_acc[t];
        if (v != 0.0f) atomicAdd(&cout[t], v);

        // block 0 zeroes a buffer that is idle this iteration:
        //  k<=4 : output buffer of iteration k+2
        //  k==5 : d_out (output of iteration 7)
        //  k==6 : g_pos[1] (restores entry invariant for the next replay)
        if (blockIdx.x == 0) {
            if (k <= 4)      g_pos[(k + 2) & 3][t] = 0.0f;
            else if (k == 5) out[t] = 0.0f;
            else if (k == 6) g_pos[1][t] = 0.0f;
        }

        if (k < NITER - 1) grid_barrier(++tgt);
    }
}

extern "C" void kernel_launch(void* const* d_in, const int* in_sizes, int n_in,
                              void* d_out, int out_size) {
    const float* clusters = (const float*)d_in[0];
    const float* heatmap  = (const float*)d_in[1];
    if (n_in >= 2 && in_sizes[0] != 2 * CC) {
        const float* tmp = clusters; clusters = heatmap; heatmap = tmp;
    }
    km_all_kernel<<<NBLK, 256>>>(clusters, heatmap, (float*)d_out);
}

// round 13
// speedup vs baseline: 1.4878x; 1.4878x over previous
#include <cuda_runtime.h>
#include <math_constants.h>

#define HH 1024
#define WW 1024
#define CC 128
#define NITER 8
#define TWO_RHO 71.6f         // 2 * sqrt(16^2 + 32^2) for a 32x64 region
#define FULLM 0xFFFFFFFFu
#define NBLK 512              // one CTA per 32-row x 64-col region

// 4 rotating cluster position buffers (row,col interleaved).
// Invariant: g_pos[1] is all-zero at kernel entry (static init covers the
// first run; block 0 re-zeroes it at k==6 each run for the next replay).
__device__ float g_pos[4][2 * CC];
// software grid barrier: counter and generation on SEPARATE 128B lines
__device__ __align__(128) unsigned g_cnt[32];
__device__ __align__(128) unsigned g_gen[32];

__device__ __forceinline__ unsigned ld_acquire_gpu(const unsigned* p) {
    unsigned v;
    asm volatile("ld.acquire.gpu.u32 %0, [%1];" : "=r"(v) : "l"(p) : "memory");
    return v;
}

// All cross-CTA data traffic is L2-native (global atomics + __ldcg), so
// scoped release/acquire atomics give full ordering with no membar/CCTL.
__device__ __forceinline__ void grid_barrier(unsigned target) {
    __syncthreads();
    if (threadIdx.x == 0) {
        unsigned old;
        asm volatile("atom.add.acq_rel.gpu.u32 %0, [%1], %2;"
                     : "=r"(old) : "l"(&g_cnt[0]), "r"(1u) : "memory");
        if (old == NBLK - 1u) {
            asm volatile("st.relaxed.gpu.u32 [%0], %1;"
                         :: "l"(&g_cnt[0]), "r"(0u) : "memory");
            asm volatile("red.add.release.gpu.u32 [%0], %1;"
                         :: "l"(&g_gen[0]), "r"(1u) : "memory");
        } else {
            unsigned g = ld_acquire_gpu(&g_gen[0]);
            int spins = 0;
            while ((int)(g - target) < 0) {
                if (++spins > 4) __nanosleep(40);   // hot-spin first, then doze
                g = ld_acquire_gpu(&g_gen[0]);
            }
        }
    }
    __syncthreads();
}

// warp-wide min of a uint (nonneg float bits are order-isomorphic)
__device__ __forceinline__ unsigned warp_min_u32(unsigned v) {
    unsigned r;
    asm volatile("redux.sync.min.u32 %0, %1, 0xffffffff;" : "=r"(r) : "r"(v));
    return r;
}

__global__ void __launch_bounds__(256, 4) km_all_kernel(
    const float* __restrict__ clusters,
    const float* __restrict__ heatmap,
    float* __restrict__ out)
{
    __shared__ float2   s_cand[CC];
    __shared__ int      s_cidx[CC];
    __shared__ float    s_acc[2 * CC];
    __shared__ unsigned s_mask[8];
    __shared__ unsigned s_wmin[8];
    __shared__ unsigned s_zmask[8];

    const int t = threadIdx.x;
    const int wid = t >> 5;
    // 32-row x 64-col region per CTA; 8 consecutive pixels per thread
    const int region_c = (blockIdx.x & 15) * 64;
    const int region_r = (blockIdx.x >> 4) * 32;
    const int row  = region_r + (t >> 3);
    const int col0 = region_c + (t & 7) * 8;
    const float frow = (float)row;
    const float fc0  = (float)col0;
    const float cy = (float)region_r + 15.5f;
    const float cx = (float)region_c + 31.5f;

    // heatmap values for this thread's 8 pixels: constant across iterations
    float h[8];
    {
        const float4 a = *reinterpret_cast<const float4*>(heatmap + row * WW + col0);
        const float4 b = *reinterpret_cast<const float4*>(heatmap + row * WW + col0 + 4);
        h[0] = a.x; h[1] = a.y; h[2] = a.z; h[3] = a.w;
        h[4] = b.x; h[5] = b.y; h[6] = b.z; h[7] = b.w;
    }

    // base generation (monotone across replays); every CTA reads it before any
    // bump can occur (a bump needs all NBLK arrivals, each preceded by a read)
    unsigned tgt = ld_acquire_gpu(&g_gen[0]);

    #pragma unroll 1
    for (int k = 0; k < NITER; ++k) {
        const float* cin = (k == 0) ? clusters : &g_pos[k & 3][0];
        float* cout = (k == NITER - 1) ? out : &g_pos[(k + 1) & 3][0];

        s_acc[t] = 0.0f;

        // ---- Phase A: per-region cull + O(1) zero-dup removal ----
        float d2c = CUDART_INF_F;
        float2 cpos = make_float2(0.f, 0.f);
        bool iszero = false;
        if (t < CC) {
            // L2 load: positions were produced by global atomics on other SMs
            cpos = __ldcg(reinterpret_cast<const float2*>(cin) + t);
            iszero = (cpos.x == 0.0f) && (cpos.y == 0.0f);
            const float dr = cy - cpos.x, dc = cx - cpos.y;
            d2c = fmaf(dr, dr, dc * dc);
        }
        const unsigned zb = __ballot_sync(FULLM, iszero);
        const unsigned mb = warp_min_u32(__float_as_uint(d2c));
        if ((t & 31) == 0) { s_wmin[wid] = mb; s_zmask[wid] = zb; }
        __syncthreads();

        unsigned mdu = s_wmin[0];
        #pragma unroll
        for (int w = 1; w < 4; ++w) mdu = min(mdu, s_wmin[w]);
        const float md2 = __uint_as_float(mdu);

        // first exactly-(0,0) cluster index (empty clusters collapse to 0);
        // later (0,0) duplicates can never win strict-< argmin -> drop them.
        // Other bitwise dups are rare and harmless (strict < keeps first).
        int firstZero = 1 << 30;
        #pragma unroll
        for (int w = 3; w >= 0; --w)
            if (s_zmask[w]) firstZero = w * 32 + (__ffs(s_zmask[w]) - 1);

        // cluster can win argmin for some pixel in region only if
        // d(center,c) <= minD + 2*rho; margin keeps fp error conservative
        const float minD = sqrtf(md2);
        const float thr  = minD + TWO_RHO + 4.0f + 1e-5f * minD;
        const float thr2 = thr * thr;

        const bool keep = (t < CC) && (d2c <= thr2) && !(iszero && t != firstZero);
        const unsigned bal = __ballot_sync(FULLM, keep);
        if ((t & 31) == 0) s_mask[wid] = bal;
        __syncthreads();
        if (keep) {
            int rank = __popc(bal & ((1u << (t & 31)) - 1u));
            for (int w = 0; w < wid; ++w) rank += __popc(s_mask[w]);
            s_cand[rank] = cpos;
            s_cidx[rank] = t;
        }
        const int ncand = __popc(s_mask[0]) + __popc(s_mask[1])
                        + __popc(s_mask[2]) + __popc(s_mask[3]);
        __syncthreads();

        // ---- Phase B: 8-pixel argmin (candidates in index order) ----
        float b[8];
        int   kk[8];
        #pragma unroll
        for (int q = 0; q < 8; ++q) { b[q] = CUDART_INF_F; kk[q] = 0; }

        #pragma unroll 2
        for (int j = 0; j < ncand; ++j) {
            const float2 cl = s_cand[j];
            const float dr = frow - cl.x;
            const float dr2 = dr * dr;
            #pragma unroll
            for (int q = 0; q < 8; ++q) {
                // ordering of max(1,sqrt(d2)) == ordering of max(1,d2)
                const float dc = (fc0 + (float)q) - cl.y;
                const float d = fmaxf(fmaf(dc, dc, dr2), 1.0f);
                if (d < b[q]) { b[q] = d; kk[q] = j; }
            }
        }

        int idx[8];
        float w8[8];
        #pragma unroll
        for (int q = 0; q < 8; ++q) {
            idx[q] = s_cidx[kk[q]];
            // weight = heatmap / max(1,sqrt(d2)) = h * rsqrt(clamped d2)
            w8[q] = h[q] * rsqrtf(b[q]);
        }

        // ---- scatter: uniform-warp fast path, run-length fallback ----
        bool uni = true;
        #pragma unroll
        for (int q = 1; q < 8; ++q) uni = uni && (idx[q] == idx[0]);
        const int  u      = __shfl_sync(FULLM, idx[0], 0);
        const bool alluni = __all_sync(FULLM, uni && (idx[0] == u));

        if (alluni) {
            float wsum = ((w8[0] + w8[1]) + (w8[2] + w8[3]))
                       + ((w8[4] + w8[5]) + (w8[6] + w8[7]));
            float csum = 0.0f;
            #pragma unroll
            for (int q = 0; q < 8; ++q) csum = fmaf(fc0 + (float)q, w8[q], csum);
            float rsum = frow * wsum;
            #pragma unroll
            for (int o = 16; o; o >>= 1) {
                rsum += __shfl_xor_sync(FULLM, rsum, o);
                csum += __shfl_xor_sync(FULLM, csum, o);
            }
            if ((t & 31) == 0) {
                atomicAdd(&s_acc[2 * u],     rsum);
                atomicAdd(&s_acc[2 * u + 1], csum);
            }
        } else {
            int cur = idx[0];
            float wsum = w8[0], cwsum = fc0 * w8[0];
            #pragma unroll
            for (int q = 1; q < 8; ++q) {
                const float fcq = fc0 + (float)q;
                if (idx[q] == cur) { wsum += w8[q]; cwsum = fmaf(fcq, w8[q], cwsum); }
                else {
                    atomicAdd(&s_acc[2 * cur],     frow * wsum);
                    atomicAdd(&s_acc[2 * cur + 1], cwsum);
                    cur = idx[q]; wsum = w8[q]; cwsum = fcq * w8[q];
                }
            }
            atomicAdd(&s_acc[2 * cur],     frow * wsum);
            atomicAdd(&s_acc[2 * cur + 1], cwsum);
        }

        __syncthreads();
        // global accumulate; skip zeros (all contributions are >= +0)
        const float v = s_acc[t];
        if (v != 0.0f) atomicAdd(&cout[t], v);

        // block 0 zeroes a buffer that is idle this iteration:
        //  k<=4 : output buffer of iteration k+2
        //  k==5 : d_out (output of iteration 7)
        //  k==6 : g_pos[1] (restores entry invariant for the next replay)
        if (blockIdx.x == 0) {
            if (k <= 4)      g_pos[(k + 2) & 3][t] = 0.0f;
            else if (k == 5) out[t] = 0.0f;
            else if (k == 6) g_pos[1][t] = 0.0f;
        }

        if (k < NITER - 1) grid_barrier(++tgt);
    }
}

extern "C" void kernel_launch(void* const* d_in, const int* in_sizes, int n_in,
                              void* d_out, int out_size) {
    const float* clusters = (const float*)d_in[0];
    const float* heatmap  = (const float*)d_in[1];
    if (n_in >= 2 && in_sizes[0] != 2 * CC) {
        const float* tmp = clusters; clusters = heatmap; heatmap = tmp;
    }
    km_all_kernel<<<NBLK, 256>>>(clusters, heatmap, (float*)d_out);
}